// round 1
// baseline (speedup 1.0000x reference)
#include <cuda_runtime.h>

// Fused 2-layer LSTM + FC for B=4096, T=256, IN=16, H1=64, H2=1 (fp32).
// One CTA handles BG=16 batch elements for all 256 timesteps.
// Thread r (0..255) owns gate row r of layer 1 (weights in registers, packed f32x2).
// Per step: gate GEMV (packed FMA, smem-broadcast operands) -> barrier ->
// activations + state update -> barrier -> layer-2 LSTM step + FC (64 threads).

#define BG 16
#define NT 256
typedef unsigned long long u64;

__device__ __forceinline__ void fma2(u64 &acc, u64 a, u64 b) {
    asm("fma.rn.f32x2 %0, %1, %2, %0;" : "+l"(acc) : "l"(a), "l"(b));
}
__device__ __forceinline__ float lo_f(u64 v) { return __uint_as_float((unsigned)v); }
__device__ __forceinline__ float hi_f(u64 v) { return __uint_as_float((unsigned)(v >> 32)); }
__device__ __forceinline__ float sigf(float x) {
    return __fdividef(1.f, 1.f + __expf(-x));
}
__device__ __forceinline__ float tanhfast(float x) {
    float e = __expf(-2.f * x);
    return __fdividef(1.f - e, 1.f + e);
}

__global__ void __launch_bounds__(NT, 2) lstm_fused(
    const float* __restrict__ x,
    const float* __restrict__ wih1, const float* __restrict__ whh1,
    const float* __restrict__ bih1, const float* __restrict__ bhh1,
    const float* __restrict__ wih2, const float* __restrict__ whh2,
    const float* __restrict__ bih2, const float* __restrict__ bhh2,
    const float* __restrict__ fcw, const float* __restrict__ fcb,
    float* __restrict__ out)
{
    __shared__ __align__(16) float sg[256][BG + 1];   // staged gate pre-activations
    __shared__ __align__(16) float h_s[BG][76];       // layer1 hidden state (pad 76: bank-spread)
    __shared__ __align__(16) float c_s[BG][64];       // layer1 cell state
    __shared__ __align__(16) float x_s[BG][16];       // current-step input
    __shared__ __align__(16) float w2_s[4][66];       // layer2 input weights, row-padded
    __shared__ float b2_s[4], whh2_s[4], fc_s[2];
    __shared__ float h2_s[BG], c2_s[BG];

    const int tid = threadIdx.x;
    const int b0 = blockIdx.x * BG;

    // ---- per-thread layer1 weights (row r = tid): 40 packed f32x2 regs ----
    u64 wih_r[8], whh_r[32];
    {
        const u64* p = (const u64*)(wih1 + tid * 16);
        #pragma unroll
        for (int i = 0; i < 8; i++) wih_r[i] = p[i];
        const u64* q = (const u64*)(whh1 + tid * 64);
        #pragma unroll
        for (int i = 0; i < 32; i++) whh_r[i] = q[i];
    }
    const float bias1 = bih1[tid] + bhh1[tid];
    const u64 bias2p = (u64)__float_as_uint(bias1);   // packed {bias, 0.0f}

    // ---- smem init ----
    for (int i = tid; i < 4 * 64; i += NT) w2_s[i >> 6][i & 63] = wih2[i];
    if (tid < 4) { b2_s[tid] = bih2[tid] + bhh2[tid]; whh2_s[tid] = whh2[tid]; }
    if (tid == 0) { fc_s[0] = fcw[0]; fc_s[1] = fcb[0]; }
    for (int i = tid; i < BG * 64; i += NT) c_s[i >> 6][i & 63] = 0.f;
    for (int i = tid; i < BG * 76; i += NT) h_s[i / 76][i % 76] = 0.f;
    if (tid < BG) { h2_s[tid] = 0.f; c2_s[tid] = 0.f; }

    // ---- x staging: thread (bq, kq) owns one element per step ----
    const int bq = tid >> 4, kq = tid & 15;
    const float* xptr = x + (long)(b0 + bq) * 4096 + kq;   // 256*16 = 4096 per batch
    x_s[bq][kq] = xptr[0];                                  // t = 0
    float xr = xptr[16];                                    // prefetch t = 1

    __syncthreads();

    for (int t = 0; t < 256; ++t) {
        // ================= layer1 gate GEMV (all 256 threads) =================
        #pragma unroll 1
        for (int bb = 0; bb < BG; bb += 4) {
            u64 a0 = bias2p, a1 = bias2p, a2 = bias2p, a3 = bias2p;
            // input contribution (16 k-values = 4 float4 broadcasts per batch)
            #pragma unroll
            for (int q = 0; q < 4; q++) {
                ulonglong2 v0 = *(const ulonglong2*)&x_s[bb + 0][q * 4];
                ulonglong2 v1 = *(const ulonglong2*)&x_s[bb + 1][q * 4];
                ulonglong2 v2 = *(const ulonglong2*)&x_s[bb + 2][q * 4];
                ulonglong2 v3 = *(const ulonglong2*)&x_s[bb + 3][q * 4];
                fma2(a0, wih_r[2 * q], v0.x); fma2(a0, wih_r[2 * q + 1], v0.y);
                fma2(a1, wih_r[2 * q], v1.x); fma2(a1, wih_r[2 * q + 1], v1.y);
                fma2(a2, wih_r[2 * q], v2.x); fma2(a2, wih_r[2 * q + 1], v2.y);
                fma2(a3, wih_r[2 * q], v3.x); fma2(a3, wih_r[2 * q + 1], v3.y);
            }
            // recurrent contribution (64 k-values = 16 float4 broadcasts per batch)
            #pragma unroll
            for (int q = 0; q < 16; q++) {
                ulonglong2 v0 = *(const ulonglong2*)&h_s[bb + 0][q * 4];
                ulonglong2 v1 = *(const ulonglong2*)&h_s[bb + 1][q * 4];
                ulonglong2 v2 = *(const ulonglong2*)&h_s[bb + 2][q * 4];
                ulonglong2 v3 = *(const ulonglong2*)&h_s[bb + 3][q * 4];
                fma2(a0, whh_r[2 * q], v0.x); fma2(a0, whh_r[2 * q + 1], v0.y);
                fma2(a1, whh_r[2 * q], v1.x); fma2(a1, whh_r[2 * q + 1], v1.y);
                fma2(a2, whh_r[2 * q], v2.x); fma2(a2, whh_r[2 * q + 1], v2.y);
                fma2(a3, whh_r[2 * q], v3.x); fma2(a3, whh_r[2 * q + 1], v3.y);
            }
            sg[tid][bb + 0] = lo_f(a0) + hi_f(a0);
            sg[tid][bb + 1] = lo_f(a1) + hi_f(a1);
            sg[tid][bb + 2] = lo_f(a2) + hi_f(a2);
            sg[tid][bb + 3] = lo_f(a3) + hi_f(a3);
        }
        __syncthreads();   // A: gates staged

        // ============ layer1 activations + state update (all threads) ============
        {
            const int u = tid & 63;
            const int bsel = tid >> 6;
            #pragma unroll
            for (int bb = 0; bb < 4; ++bb) {
                const int b = bsel * 4 + bb;
                float gi = sg[u][b];
                float gf = sg[64 + u][b];
                float gg = sg[128 + u][b];
                float go = sg[192 + u][b];
                float i_ = sigf(gi), f_ = sigf(gf);
                float g_ = tanhfast(gg), o_ = sigf(go);
                float c = f_ * c_s[b][u] + i_ * g_;
                c_s[b][u] = c;
                h_s[b][u] = o_ * tanhfast(c);
            }
            // stage x for t+1, prefetch t+2
            if (t < 255) x_s[bq][kq] = xr;
            if (t < 254) xr = xptr[(t + 2) * 16];
        }
        __syncthreads();   // B: h_s(t) and x_s(t+1) ready

        // ============ layer2 LSTM step + FC (threads 0..63) ============
        if (tid < 64) {
            const int j = tid & 3;        // gate index i,f,g,o
            const int b = tid >> 2;       // batch within CTA
            u64 acc = (u64)__float_as_uint(b2_s[j]);
            const u64* wrow = (const u64*)&w2_s[j][0];
            const float* hb = &h_s[b][0];
            #pragma unroll
            for (int q = 0; q < 32; q++) {
                u64 hv = *(const u64*)&hb[q * 2];
                fma2(acc, wrow[q], hv);
            }
            float gj = lo_f(acc) + hi_f(acc) + whh2_s[j] * h2_s[b];
            const int lb = (tid & 31) & ~3;
            float gi = __shfl_sync(0xffffffffu, gj, lb + 0);
            float gf = __shfl_sync(0xffffffffu, gj, lb + 1);
            float gg = __shfl_sync(0xffffffffu, gj, lb + 2);
            float go = __shfl_sync(0xffffffffu, gj, lb + 3);
            if (j == 0) {
                float i_ = sigf(gi), f_ = sigf(gf);
                float g_ = tanhfast(gg), o_ = sigf(go);
                float c2 = f_ * c2_s[b] + i_ * g_;
                c2_s[b] = c2;
                float h2 = o_ * tanhfast(c2);
                h2_s[b] = h2;
                out[(long)(b0 + b) * 256 + t] = fc_s[0] * h2 + fc_s[1];
            }
        }
        // next iteration's barrier A orders layer2 h_s reads vs. activation writes
    }
}

extern "C" void kernel_launch(void* const* d_in, const int* in_sizes, int n_in,
                              void* d_out, int out_size) {
    (void)in_sizes; (void)n_in; (void)out_size;
    const float* x    = (const float*)d_in[0];
    const float* wih1 = (const float*)d_in[1];
    const float* whh1 = (const float*)d_in[2];
    const float* bih1 = (const float*)d_in[3];
    const float* bhh1 = (const float*)d_in[4];
    const float* wih2 = (const float*)d_in[5];
    const float* whh2 = (const float*)d_in[6];
    const float* bih2 = (const float*)d_in[7];
    const float* bhh2 = (const float*)d_in[8];
    const float* fcw  = (const float*)d_in[9];
    const float* fcb  = (const float*)d_in[10];
    float* out = (float*)d_out;

    lstm_fused<<<4096 / BG, NT>>>(x, wih1, whh1, bih1, bhh1,
                                  wih2, whh2, bih2, bhh2, fcw, fcb, out);
}

// round 5
// speedup vs baseline: 1.2000x; 1.2000x over previous
#include <cuda_runtime.h>

// Fused 2-layer LSTM + FC for B=4096, T=256, IN=16, H1=64, H2=1 (fp32).
// R2 variant: one CTA = 128 threads handles BG=16 batches for all 256 steps.
// Thread r owns gate rows r and r+128 (2x80 weights in packed f32x2 regs) ->
// each smem activation load feeds 4 packed FMAs (was 2) -> LDS pipe unbound.

#define BG 16
#define NT 128
typedef unsigned long long u64;

__device__ __forceinline__ void fma2(u64 &acc, u64 a, u64 b) {
    asm("fma.rn.f32x2 %0, %1, %2, %0;" : "+l"(acc) : "l"(a), "l"(b));
}
__device__ __forceinline__ float lo_f(u64 v) { return __uint_as_float((unsigned)v); }
__device__ __forceinline__ float hi_f(u64 v) { return __uint_as_float((unsigned)(v >> 32)); }
__device__ __forceinline__ float sigf(float x) {
    return __fdividef(1.f, 1.f + __expf(-x));
}
__device__ __forceinline__ float tanhfast(float x) {
    float e = __expf(-2.f * x);
    return __fdividef(1.f - e, 1.f + e);
}

__global__ void __launch_bounds__(NT, 2) lstm_fused(
    const float* __restrict__ x,
    const float* __restrict__ wih1, const float* __restrict__ whh1,
    const float* __restrict__ bih1, const float* __restrict__ bhh1,
    const float* __restrict__ wih2, const float* __restrict__ whh2,
    const float* __restrict__ bih2, const float* __restrict__ bhh2,
    const float* __restrict__ fcw, const float* __restrict__ fcb,
    float* __restrict__ out)
{
    __shared__ __align__(16) float sg[256][BG + 1];   // staged gate pre-activations
    __shared__ __align__(16) float h_s[BG][76];       // layer1 hidden state
    __shared__ __align__(16) float c_s[BG][64];       // layer1 cell state
    __shared__ __align__(16) float x_s[BG][16];       // current-step input
    __shared__ __align__(16) float w2_s[4][66];       // layer2 input weights
    __shared__ float b2_s[4], whh2_s[4], fc_s[2];
    __shared__ float h2_s[BG], c2_s[BG];

    const int tid = threadIdx.x;
    const int b0 = blockIdx.x * BG;

    // ---- per-thread layer1 weights: rows tid and tid+128, packed f32x2 ----
    u64 wiA[8], wiB[8], whA[32], whB[32];
    {
        const u64* pA = (const u64*)(wih1 + tid * 16);
        const u64* pB = (const u64*)(wih1 + (tid + 128) * 16);
        #pragma unroll
        for (int i = 0; i < 8; i++) { wiA[i] = pA[i]; wiB[i] = pB[i]; }
        const u64* qA = (const u64*)(whh1 + tid * 64);
        const u64* qB = (const u64*)(whh1 + (tid + 128) * 64);
        #pragma unroll
        for (int i = 0; i < 32; i++) { whA[i] = qA[i]; whB[i] = qB[i]; }
    }
    const u64 biasA = (u64)__float_as_uint(bih1[tid] + bhh1[tid]);
    const u64 biasB = (u64)__float_as_uint(bih1[tid + 128] + bhh1[tid + 128]);

    // ---- smem init ----
    for (int i = tid; i < 4 * 64; i += NT) w2_s[i >> 6][i & 63] = wih2[i];
    if (tid < 4) { b2_s[tid] = bih2[tid] + bhh2[tid]; whh2_s[tid] = whh2[tid]; }
    if (tid == 0) { fc_s[0] = fcw[0]; fc_s[1] = fcb[0]; }
    for (int i = tid; i < BG * 64; i += NT) c_s[i >> 6][i & 63] = 0.f;
    for (int i = tid; i < BG * 76; i += NT) h_s[i / 76][i % 76] = 0.f;
    if (tid < BG) { h2_s[tid] = 0.f; c2_s[tid] = 0.f; }

    // ---- x staging: thread owns (bq, kq) and (bq+8, kq), one elem per step ----
    const int bq = tid >> 4, kq = tid & 15;
    const float* xpA = x + (long)(b0 + bq) * 4096 + kq;       // T*IN = 4096
    const float* xpB = x + (long)(b0 + bq + 8) * 4096 + kq;
    x_s[bq][kq] = xpA[0];
    x_s[bq + 8][kq] = xpB[0];
    float xrA = xpA[16], xrB = xpB[16];                        // prefetch t=1

    __syncthreads();

    for (int t = 0; t < 256; ++t) {
        // ============ layer1 gate GEMV: 2 rows x 16 batches per thread ============
        #pragma unroll 1
        for (int bb = 0; bb < BG; bb += 4) {
            u64 aA0 = biasA, aA1 = biasA, aA2 = biasA, aA3 = biasA;
            u64 aB0 = biasB, aB1 = biasB, aB2 = biasB, aB3 = biasB;
            // input contribution: 16 k per batch
            #pragma unroll
            for (int q = 0; q < 4; q++) {
                const u64 wA0 = wiA[2 * q], wA1 = wiA[2 * q + 1];
                const u64 wB0 = wiB[2 * q], wB1 = wiB[2 * q + 1];
                ulonglong2 v0 = *(const ulonglong2*)&x_s[bb + 0][q * 4];
                ulonglong2 v1 = *(const ulonglong2*)&x_s[bb + 1][q * 4];
                ulonglong2 v2 = *(const ulonglong2*)&x_s[bb + 2][q * 4];
                ulonglong2 v3 = *(const ulonglong2*)&x_s[bb + 3][q * 4];
                fma2(aA0, wA0, v0.x); fma2(aA0, wA1, v0.y);
                fma2(aB0, wB0, v0.x); fma2(aB0, wB1, v0.y);
                fma2(aA1, wA0, v1.x); fma2(aA1, wA1, v1.y);
                fma2(aB1, wB0, v1.x); fma2(aB1, wB1, v1.y);
                fma2(aA2, wA0, v2.x); fma2(aA2, wA1, v2.y);
                fma2(aB2, wB0, v2.x); fma2(aB2, wB1, v2.y);
                fma2(aA3, wA0, v3.x); fma2(aA3, wA1, v3.y);
                fma2(aB3, wB0, v3.x); fma2(aB3, wB1, v3.y);
            }
            // recurrent contribution: 64 k per batch
            #pragma unroll
            for (int q = 0; q < 16; q++) {
                const u64 wA0 = whA[2 * q], wA1 = whA[2 * q + 1];
                const u64 wB0 = whB[2 * q], wB1 = whB[2 * q + 1];
                ulonglong2 v0 = *(const ulonglong2*)&h_s[bb + 0][q * 4];
                ulonglong2 v1 = *(const ulonglong2*)&h_s[bb + 1][q * 4];
                ulonglong2 v2 = *(const ulonglong2*)&h_s[bb + 2][q * 4];
                ulonglong2 v3 = *(const ulonglong2*)&h_s[bb + 3][q * 4];
                fma2(aA0, wA0, v0.x); fma2(aA0, wA1, v0.y);
                fma2(aB0, wB0, v0.x); fma2(aB0, wB1, v0.y);
                fma2(aA1, wA0, v1.x); fma2(aA1, wA1, v1.y);
                fma2(aB1, wB0, v1.x); fma2(aB1, wB1, v1.y);
                fma2(aA2, wA0, v2.x); fma2(aA2, wA1, v2.y);
                fma2(aB2, wB0, v2.x); fma2(aB2, wB1, v2.y);
                fma2(aA3, wA0, v3.x); fma2(aA3, wA1, v3.y);
                fma2(aB3, wB0, v3.x); fma2(aB3, wB1, v3.y);
            }
            sg[tid][bb + 0] = lo_f(aA0) + hi_f(aA0);
            sg[tid][bb + 1] = lo_f(aA1) + hi_f(aA1);
            sg[tid][bb + 2] = lo_f(aA2) + hi_f(aA2);
            sg[tid][bb + 3] = lo_f(aA3) + hi_f(aA3);
            sg[128 + tid][bb + 0] = lo_f(aB0) + hi_f(aB0);
            sg[128 + tid][bb + 1] = lo_f(aB1) + hi_f(aB1);
            sg[128 + tid][bb + 2] = lo_f(aB2) + hi_f(aB2);
            sg[128 + tid][bb + 3] = lo_f(aB3) + hi_f(aB3);
        }
        __syncthreads();   // A: gates staged

        // ============ layer1 activations + state update (128 threads) ============
        {
            const int u = tid & 63;
            const int bsel = tid >> 6;           // 0 or 1 -> 8 batches each
            #pragma unroll
            for (int bb = 0; bb < 8; ++bb) {
                const int b = bsel * 8 + bb;
                float gi = sg[u][b];
                float gf = sg[64 + u][b];
                float gg = sg[128 + u][b];
                float go = sg[192 + u][b];
                float i_ = sigf(gi), f_ = sigf(gf);
                float g_ = tanhfast(gg), o_ = sigf(go);
                float c = f_ * c_s[b][u] + i_ * g_;
                c_s[b][u] = c;
                h_s[b][u] = o_ * tanhfast(c);
            }
            // stage x for t+1, prefetch t+2
            if (t < 255) { x_s[bq][kq] = xrA; x_s[bq + 8][kq] = xrB; }
            if (t < 254) { xrA = xpA[(t + 2) * 16]; xrB = xpB[(t + 2) * 16]; }
        }
        __syncthreads();   // B: h_s(t) and x_s(t+1) ready

        // ============ layer2 LSTM step + FC (threads 0..63) ============
        if (tid < 64) {
            const int j = tid & 3;        // gate i,f,g,o
            const int b = tid >> 2;       // batch within CTA
            u64 acc = (u64)__float_as_uint(b2_s[j]);
            const u64* wrow = (const u64*)&w2_s[j][0];
            const float* hb = &h_s[b][0];
            #pragma unroll
            for (int q = 0; q < 32; q++) {
                u64 hv = *(const u64*)&hb[q * 2];
                fma2(acc, wrow[q], hv);
            }
            float gj = lo_f(acc) + hi_f(acc) + whh2_s[j] * h2_s[b];
            const int lb = (tid & 31) & ~3;
            float gi = __shfl_sync(0xffffffffu, gj, lb + 0);
            float gf = __shfl_sync(0xffffffffu, gj, lb + 1);
            float gg = __shfl_sync(0xffffffffu, gj, lb + 2);
            float go = __shfl_sync(0xffffffffu, gj, lb + 3);
            if (j == 0) {
                float i_ = sigf(gi), f_ = sigf(gf);
                float g_ = tanhfast(gg), o_ = sigf(go);
                float c2 = f_ * c2_s[b] + i_ * g_;
                c2_s[b] = c2;
                float h2 = o_ * tanhfast(c2);
                h2_s[b] = h2;
                out[(long)(b0 + b) * 256 + t] = fc_s[0] * h2 + fc_s[1];
            }
        }
        // next iteration's barrier A orders layer2 h_s reads vs. activation writes
    }
}

extern "C" void kernel_launch(void* const* d_in, const int* in_sizes, int n_in,
                              void* d_out, int out_size) {
    (void)in_sizes; (void)n_in; (void)out_size;
    const float* x    = (const float*)d_in[0];
    const float* wih1 = (const float*)d_in[1];
    const float* whh1 = (const float*)d_in[2];
    const float* bih1 = (const float*)d_in[3];
    const float* bhh1 = (const float*)d_in[4];
    const float* wih2 = (const float*)d_in[5];
    const float* whh2 = (const float*)d_in[6];
    const float* bih2 = (const float*)d_in[7];
    const float* bhh2 = (const float*)d_in[8];
    const float* fcw  = (const float*)d_in[9];
    const float* fcb  = (const float*)d_in[10];
    float* out = (float*)d_out;

    lstm_fused<<<4096 / BG, NT>>>(x, wih1, whh1, bih1, bhh1,
                                  wih2, whh2, bih2, bhh2, fcw, fcb, out);
}

// round 6
// speedup vs baseline: 1.2628x; 1.0524x over previous
#include <cuda_runtime.h>

// Fused 2-layer LSTM + FC for B=4096, T=256, IN=16, H1=64, H2=1 (fp32).
// K-split variant: CTA = 256 threads, BG=16 batches, 2 CTAs/SM (16 warps).
// Thread t: rows (t&127, (t&127)+128), k-half (t>>7) of the 80-wide dot
// ([x(16) | h(64)] fused in smem). 80 weight regs/thread -> regs <= 128.
// Partial sums combined during the activation phase.

#define BG 16
#define NT 256
#define HXW 84   // hx row stride in floats (21*16B)
typedef unsigned long long u64;

__device__ __forceinline__ void fma2(u64 &acc, u64 a, u64 b) {
    asm("fma.rn.f32x2 %0, %1, %2, %0;" : "+l"(acc) : "l"(a), "l"(b));
}
__device__ __forceinline__ float lo_f(u64 v) { return __uint_as_float((unsigned)v); }
__device__ __forceinline__ float hi_f(u64 v) { return __uint_as_float((unsigned)(v >> 32)); }
__device__ __forceinline__ float sigf(float x) {
    return __fdividef(1.f, 1.f + __expf(-x));
}
__device__ __forceinline__ float tanhfast(float x) {
    float e = __expf(-2.f * x);
    return __fdividef(1.f - e, 1.f + e);
}

__global__ void __launch_bounds__(NT, 2) lstm_fused(
    const float* __restrict__ x,
    const float* __restrict__ wih1, const float* __restrict__ whh1,
    const float* __restrict__ bih1, const float* __restrict__ bhh1,
    const float* __restrict__ wih2, const float* __restrict__ whh2,
    const float* __restrict__ bih2, const float* __restrict__ bhh2,
    const float* __restrict__ fcw, const float* __restrict__ fcb,
    float* __restrict__ out)
{
    __shared__ __align__(16) float sgP[2][256][BG + 1]; // partial gate sums (khalf 0/1)
    __shared__ __align__(16) float hx_s[BG][HXW];       // [0:16)=x(t), [16:80)=h(t-1)
    __shared__ __align__(16) float c_s[BG][64];         // layer1 cell state
    __shared__ __align__(16) float w2_s[4][66];         // layer2 input weights
    __shared__ float b2_s[4], whh2_s[4], fc_s[2];
    __shared__ float h2_s[BG], c2_s[BG];

    const int tid = threadIdx.x;
    const int b0 = blockIdx.x * BG;
    const int r = tid & 127;          // row pair (r, r+128)
    const int khalf = tid >> 7;       // 0: floats [0,40)  1: floats [40,80)
    const int koff = khalf * 40;      // float offset into hx row

    // ---- per-thread weights: 20 u64 per row, rows r and r+128 ----
    // 80-float concat per row: [wih1[row,0:16] | whh1[row,0:64]]
    u64 wA[20], wB[20];
    if (khalf == 0) {
        const u64* wiA = (const u64*)(wih1 + r * 16);
        const u64* wiB = (const u64*)(wih1 + (r + 128) * 16);
        const u64* whA = (const u64*)(whh1 + r * 64);
        const u64* whB = (const u64*)(whh1 + (r + 128) * 64);
        #pragma unroll
        for (int m = 0; m < 8; m++)  { wA[m] = wiA[m]; wB[m] = wiB[m]; }
        #pragma unroll
        for (int m = 8; m < 20; m++) { wA[m] = whA[m - 8]; wB[m] = whB[m - 8]; }
    } else {
        const u64* whA = (const u64*)(whh1 + r * 64);
        const u64* whB = (const u64*)(whh1 + (r + 128) * 64);
        #pragma unroll
        for (int m = 0; m < 20; m++) { wA[m] = whA[m + 12]; wB[m] = whB[m + 12]; }
    }
    // bias only in khalf0 partial
    const u64 initA = khalf ? 0ull : (u64)__float_as_uint(bih1[r] + bhh1[r]);
    const u64 initB = khalf ? 0ull : (u64)__float_as_uint(bih1[r + 128] + bhh1[r + 128]);

    // ---- smem init ----
    for (int i = tid; i < 4 * 64; i += NT) w2_s[i >> 6][i & 63] = wih2[i];
    if (tid < 4) { b2_s[tid] = bih2[tid] + bhh2[tid]; whh2_s[tid] = whh2[tid]; }
    if (tid == 0) { fc_s[0] = fcw[0]; fc_s[1] = fcb[0]; }
    for (int i = tid; i < BG * 64; i += NT) c_s[i >> 6][i & 63] = 0.f;
    for (int i = tid; i < BG * HXW; i += NT) hx_s[i / HXW][i % HXW] = 0.f;
    if (tid < BG) { h2_s[tid] = 0.f; c2_s[tid] = 0.f; }
    __syncthreads();   // hx zero visible before x staging writes below mix in

    // ---- x staging: thread (bq = tid>>4, kq = tid&15) owns one element/step ----
    const int bq = tid >> 4, kq = tid & 15;
    const float* xptr = x + (long)(b0 + bq) * 4096 + kq;   // T*IN = 4096
    hx_s[bq][kq] = xptr[0];                                 // t = 0
    float xr = xptr[16];                                    // prefetch t = 1

    __syncthreads();

    for (int t = 0; t < 256; ++t) {
        // ===== layer1 gate GEMV: 2 rows x 40 k x 16 batches per thread =====
        #pragma unroll 1
        for (int bb = 0; bb < BG; bb += 4) {
            u64 aA0 = initA, aA1 = initA, aA2 = initA, aA3 = initA;
            u64 aB0 = initB, aB1 = initB, aB2 = initB, aB3 = initB;
            const float* h0 = &hx_s[bb + 0][koff];
            const float* h1 = &hx_s[bb + 1][koff];
            const float* h2 = &hx_s[bb + 2][koff];
            const float* h3 = &hx_s[bb + 3][koff];
            #pragma unroll
            for (int q = 0; q < 10; q++) {
                const u64 w0 = wA[2 * q], w1 = wA[2 * q + 1];
                const u64 u0 = wB[2 * q], u1 = wB[2 * q + 1];
                ulonglong2 v0 = *(const ulonglong2*)(h0 + q * 4);
                ulonglong2 v1 = *(const ulonglong2*)(h1 + q * 4);
                ulonglong2 v2 = *(const ulonglong2*)(h2 + q * 4);
                ulonglong2 v3 = *(const ulonglong2*)(h3 + q * 4);
                fma2(aA0, w0, v0.x); fma2(aA0, w1, v0.y);
                fma2(aB0, u0, v0.x); fma2(aB0, u1, v0.y);
                fma2(aA1, w0, v1.x); fma2(aA1, w1, v1.y);
                fma2(aB1, u0, v1.x); fma2(aB1, u1, v1.y);
                fma2(aA2, w0, v2.x); fma2(aA2, w1, v2.y);
                fma2(aB2, u0, v2.x); fma2(aB2, u1, v2.y);
                fma2(aA3, w0, v3.x); fma2(aA3, w1, v3.y);
                fma2(aB3, u0, v3.x); fma2(aB3, u1, v3.y);
            }
            sgP[khalf][r][bb + 0] = lo_f(aA0) + hi_f(aA0);
            sgP[khalf][r][bb + 1] = lo_f(aA1) + hi_f(aA1);
            sgP[khalf][r][bb + 2] = lo_f(aA2) + hi_f(aA2);
            sgP[khalf][r][bb + 3] = lo_f(aA3) + hi_f(aA3);
            sgP[khalf][128 + r][bb + 0] = lo_f(aB0) + hi_f(aB0);
            sgP[khalf][128 + r][bb + 1] = lo_f(aB1) + hi_f(aB1);
            sgP[khalf][128 + r][bb + 2] = lo_f(aB2) + hi_f(aB2);
            sgP[khalf][128 + r][bb + 3] = lo_f(aB3) + hi_f(aB3);
        }
        __syncthreads();   // A: partial gates staged

        // ===== layer1 activations + state update (256 threads, 4 units each) =====
        {
            const int u = tid & 63;
            const int bgrp = tid >> 6;           // 4 batches each
            #pragma unroll
            for (int j = 0; j < 4; ++j) {
                const int b = bgrp * 4 + j;
                float gi = sgP[0][u][b]        + sgP[1][u][b];
                float gf = sgP[0][64 + u][b]   + sgP[1][64 + u][b];
                float gg = sgP[0][128 + u][b]  + sgP[1][128 + u][b];
                float go = sgP[0][192 + u][b]  + sgP[1][192 + u][b];
                float i_ = sigf(gi), f_ = sigf(gf);
                float g_ = tanhfast(gg), o_ = sigf(go);
                float c = f_ * c_s[b][u] + i_ * g_;
                c_s[b][u] = c;
                hx_s[b][16 + u] = o_ * tanhfast(c);
            }
            // stage x for t+1, prefetch t+2 (disjoint from h region)
            if (t < 255) hx_s[bq][kq] = xr;
            if (t < 254) xr = xptr[(t + 2) * 16];
        }
        __syncthreads();   // B: h(t) and x(t+1) ready

        // ===== layer2 LSTM step + FC (threads 0..63) =====
        if (tid < 64) {
            const int j = tid & 3;        // gate i,f,g,o
            const int b = tid >> 2;       // batch within CTA
            u64 acc = (u64)__float_as_uint(b2_s[j]);
            const u64* wrow = (const u64*)&w2_s[j][0];
            const float* hb = &hx_s[b][16];
            #pragma unroll
            for (int q = 0; q < 32; q++) {
                u64 hv = *(const u64*)&hb[q * 2];
                fma2(acc, wrow[q], hv);
            }
            float gj = lo_f(acc) + hi_f(acc) + whh2_s[j] * h2_s[b];
            const int lb = (tid & 31) & ~3;
            float gi = __shfl_sync(0xffffffffu, gj, lb + 0);
            float gf = __shfl_sync(0xffffffffu, gj, lb + 1);
            float gg = __shfl_sync(0xffffffffu, gj, lb + 2);
            float go = __shfl_sync(0xffffffffu, gj, lb + 3);
            if (j == 0) {
                float i_ = sigf(gi), f_ = sigf(gf);
                float g_ = tanhfast(gg), o_ = sigf(go);
                float c2 = f_ * c2_s[b] + i_ * g_;
                c2_s[b] = c2;
                float h2v = o_ * tanhfast(c2);
                h2_s[b] = h2v;
                out[(long)(b0 + b) * 256 + t] = fc_s[0] * h2v + fc_s[1];
            }
        }
        // next iteration's barrier A orders layer2 hx reads vs. activation writes
    }
}

extern "C" void kernel_launch(void* const* d_in, const int* in_sizes, int n_in,
                              void* d_out, int out_size) {
    (void)in_sizes; (void)n_in; (void)out_size;
    const float* x    = (const float*)d_in[0];
    const float* wih1 = (const float*)d_in[1];
    const float* whh1 = (const float*)d_in[2];
    const float* bih1 = (const float*)d_in[3];
    const float* bhh1 = (const float*)d_in[4];
    const float* wih2 = (const float*)d_in[5];
    const float* whh2 = (const float*)d_in[6];
    const float* bih2 = (const float*)d_in[7];
    const float* bhh2 = (const float*)d_in[8];
    const float* fcw  = (const float*)d_in[9];
    const float* fcb  = (const float*)d_in[10];
    float* out = (float*)d_out;

    lstm_fused<<<4096 / BG, NT>>>(x, wih1, whh1, bih1, bhh1,
                                  wih2, whh2, bih2, bhh2, fcw, fcb, out);
}